// round 2
// baseline (speedup 1.0000x reference)
#include <cuda_runtime.h>
#include <math.h>

#define N_NODES 10000
#define N_EDGES 320000
#define H2 256          // node feature width
#define H4 512          // concat width

// Scratch (static __device__ arrays -- no allocation allowed)
__device__ float g_S[N_NODES * H2];              // sum of x[src] per dst
__device__ int   g_deg[N_NODES];                 // in-degree per dst
__device__ float g_cat[(size_t)N_NODES * H4];    // [x, deg*x - S]
__device__ float g_h[N_NODES * H2];              // GEMM1 output

// ---------------------------------------------------------------------------
// Zero scratch
// ---------------------------------------------------------------------------
__global__ void zero_kernel() {
    int idx = blockIdx.x * blockDim.x + threadIdx.x;
    const int total4 = N_NODES * H2 / 4;   // 640000 float4
    if (idx < total4) ((float4*)g_S)[idx] = make_float4(0.f, 0.f, 0.f, 0.f);
    if (idx < N_NODES) g_deg[idx] = 0;
}

// ---------------------------------------------------------------------------
// Edge scatter: one warp per edge.
//   S[dst] += x[src]   (vectorized f32x4 reduction, no return)
//   deg[dst] += 1
// ---------------------------------------------------------------------------
__global__ void scatter_kernel(const float* __restrict__ x,
                               const int* __restrict__ esrc,
                               const int* __restrict__ edst) {
    int gtid = blockIdx.x * blockDim.x + threadIdx.x;
    int e    = gtid >> 5;
    int lane = gtid & 31;
    if (e >= N_EDGES) return;
    int s = esrc[e];
    int d = edst[e];
    if (lane == 0) atomicAdd(&g_deg[d], 1);
    const float4* xs = (const float4*)(x + (size_t)s * H2);
    float4*       Sd = (float4*)(g_S + (size_t)d * H2);
#pragma unroll
    for (int i = 0; i < 2; ++i) {
        int c = lane + 32 * i;           // 64 float4 chunks per edge
        float4 v = xs[c];
        asm volatile("red.global.add.v4.f32 [%0], {%1, %2, %3, %4};"
                     :: "l"(Sd + c), "f"(v.x), "f"(v.y), "f"(v.z), "f"(v.w)
                     : "memory");
    }
}

// ---------------------------------------------------------------------------
// Build cat = [x, deg*x - S]   (pooled = deg*x - S)
// ---------------------------------------------------------------------------
__global__ void cat_kernel(const float* __restrict__ x) {
    int idx = blockIdx.x * blockDim.x + threadIdx.x;   // over N_NODES*64
    if (idx >= N_NODES * (H2 / 4)) return;
    int n = idx >> 6;      // node
    int c = idx & 63;      // float4 chunk within row
    float4 xv = ((const float4*)x)[idx];
    float4* cat4 = (float4*)g_cat;
    cat4[(size_t)n * 128 + c] = xv;
    float dg = (float)g_deg[n];
    float4 sv = ((const float4*)g_S)[idx];
    float4 pv = make_float4(dg * xv.x - sv.x, dg * xv.y - sv.y,
                            dg * xv.z - sv.z, dg * xv.w - sv.w);
    cat4[(size_t)n * 128 + 64 + c] = pv;
}

// ---------------------------------------------------------------------------
// fp32 SGEMM: C[M,N] = A[M,K] @ B[K,N] + bias, optional tanh.
// Tile 128x128x8, 256 threads, 8x8 per thread.
// Requires: N multiple of 128 on this problem (N=256), K multiple of 8.
// ---------------------------------------------------------------------------
template<int TANH>
__global__ __launch_bounds__(256)
void sgemm_kernel(const float* __restrict__ A, const float* __restrict__ B,
                  const float* __restrict__ bias, float* __restrict__ C,
                  int M, int N, int K) {
    __shared__ float As[8][128];   // transposed A tile
    __shared__ float Bs[8][128];

    int tid = threadIdx.x;
    int tx = tid & 15;         // 0..15 -> 8 output cols each
    int ty = tid >> 4;         // 0..15 -> 8 output rows each
    int m0 = blockIdx.x * 128;
    int n0 = blockIdx.y * 128;

    // A-tile load mapping: 128 rows x 8 cols = 256 float4 (one per thread)
    int arow = tid >> 1;            // 0..127
    int aseg = (tid & 1) * 4;       // 0 or 4
    // B-tile load mapping: 8 rows x 128 cols = 256 float4
    int brow = tid >> 5;            // 0..7
    int bcol = (tid & 31) * 4;      // 0..124

    float acc[8][8];
#pragma unroll
    for (int i = 0; i < 8; ++i)
#pragma unroll
        for (int j = 0; j < 8; ++j) acc[i][j] = 0.f;

    for (int k0 = 0; k0 < K; k0 += 8) {
        float4 av = make_float4(0.f, 0.f, 0.f, 0.f);
        int am = m0 + arow;
        if (am < M) av = *(const float4*)(A + (size_t)am * K + k0 + aseg);
        As[aseg + 0][arow] = av.x;
        As[aseg + 1][arow] = av.y;
        As[aseg + 2][arow] = av.z;
        As[aseg + 3][arow] = av.w;

        float4 bv = *(const float4*)(B + (size_t)(k0 + brow) * N + n0 + bcol);
        *(float4*)&Bs[brow][bcol] = bv;
        __syncthreads();

#pragma unroll
        for (int k = 0; k < 8; ++k) {
            float a[8], b[8];
            *(float4*)&a[0] = *(const float4*)&As[k][ty * 8];
            *(float4*)&a[4] = *(const float4*)&As[k][ty * 8 + 4];
            *(float4*)&b[0] = *(const float4*)&Bs[k][tx * 8];
            *(float4*)&b[4] = *(const float4*)&Bs[k][tx * 8 + 4];
#pragma unroll
            for (int i = 0; i < 8; ++i)
#pragma unroll
                for (int j = 0; j < 8; ++j)
                    acc[i][j] += a[i] * b[j];
        }
        __syncthreads();
    }

    // Epilogue: bias (+ tanh), vectorized stores
#pragma unroll
    for (int i = 0; i < 8; ++i) {
        int m = m0 + ty * 8 + i;
        if (m < M) {
            float* Crow = C + (size_t)m * N + n0 + tx * 8;
            const float* bptr = bias + n0 + tx * 8;
#pragma unroll
            for (int jj = 0; jj < 2; ++jj) {
                float4 r;
                r.x = acc[i][jj * 4 + 0] + bptr[jj * 4 + 0];
                r.y = acc[i][jj * 4 + 1] + bptr[jj * 4 + 1];
                r.z = acc[i][jj * 4 + 2] + bptr[jj * 4 + 2];
                r.w = acc[i][jj * 4 + 3] + bptr[jj * 4 + 3];
                if (TANH) {
                    r.x = tanhf(r.x); r.y = tanhf(r.y);
                    r.z = tanhf(r.z); r.w = tanhf(r.w);
                }
                *(float4*)(Crow + jj * 4) = r;
            }
        }
    }
}

// ---------------------------------------------------------------------------
extern "C" void kernel_launch(void* const* d_in, const int* in_sizes, int n_in,
                              void* d_out, int out_size) {
    const float* x    = (const float*)d_in[0];   // node_feats [10000,256]
    const float* W1   = (const float*)d_in[1];   // [512,256]
    const float* b1   = (const float*)d_in[2];   // [256]
    const float* W2   = (const float*)d_in[3];   // [256,256]
    const float* b2   = (const float*)d_in[4];   // [256]
    const int*   esrc = (const int*)d_in[5];     // [320000]
    const int*   edst = (const int*)d_in[6];     // [320000]
    float*       out  = (float*)d_out;           // [10000,256]

    void *cat_p = nullptr, *h_p = nullptr;
    cudaGetSymbolAddress(&cat_p, g_cat);
    cudaGetSymbolAddress(&h_p, g_h);
    float* catf = (float*)cat_p;
    float* hf   = (float*)h_p;

    // 1) zero scratch
    {
        int total = N_NODES * H2 / 4;   // covers g_deg too (640000 > 10000)
        zero_kernel<<<(total + 255) / 256, 256>>>();
    }
    // 2) edge scatter (deg + S)
    scatter_kernel<<<(N_EDGES * 32) / 256, 256>>>(x, esrc, edst);
    // 3) cat = [x, deg*x - S]
    cat_kernel<<<(N_NODES * 64 + 255) / 256, 256>>>(x);
    // 4) h = cat @ W1 + b1
    {
        dim3 grid((N_NODES + 127) / 128, H2 / 128);
        sgemm_kernel<0><<<grid, 256>>>(catf, W1, b1, hf, N_NODES, H2, H4);
    }
    // 5) out = tanh(h @ W2 + b2)
    {
        dim3 grid((N_NODES + 127) / 128, H2 / 128);
        sgemm_kernel<1><<<grid, 256>>>(hf, W2, b2, out, N_NODES, H2, H2);
    }
}

// round 4
// speedup vs baseline: 1.5087x; 1.5087x over previous
#include <cuda_runtime.h>
#include <math.h>

#define N_NODES 10000
#define N_EDGES 320000
#define H2 256          // node feature width
#define H4 512          // concat width

// Scratch (static __device__ arrays -- no allocation allowed)
__device__ float g_S[N_NODES * H2];              // sum of x[src] per dst
__device__ int   g_deg[N_NODES];                 // in-degree per dst
__device__ float g_cat[(size_t)N_NODES * H4];    // [x, deg*x - S]
__device__ float g_h[N_NODES * H2];              // GEMM1 output

// ---------------------------------------------------------------------------
// Zero scratch
// ---------------------------------------------------------------------------
__global__ void zero_kernel() {
    int idx = blockIdx.x * blockDim.x + threadIdx.x;
    const int total4 = N_NODES * H2 / 4;   // 640000 float4
    if (idx < total4) ((float4*)g_S)[idx] = make_float4(0.f, 0.f, 0.f, 0.f);
    if (idx < N_NODES) g_deg[idx] = 0;
}

// ---------------------------------------------------------------------------
// Edge scatter: one warp per edge.
//   S[dst] += x[src]   (vectorized f32x4 reduction, no return)
//   deg[dst] += 1
// ---------------------------------------------------------------------------
__global__ void scatter_kernel(const float* __restrict__ x,
                               const int* __restrict__ esrc,
                               const int* __restrict__ edst) {
    int gtid = blockIdx.x * blockDim.x + threadIdx.x;
    int e    = gtid >> 5;
    int lane = gtid & 31;
    if (e >= N_EDGES) return;
    int s = esrc[e];
    int d = edst[e];
    if (lane == 0) atomicAdd(&g_deg[d], 1);
    const float4* xs = (const float4*)(x + (size_t)s * H2);
    float4*       Sd = (float4*)(g_S + (size_t)d * H2);
#pragma unroll
    for (int i = 0; i < 2; ++i) {
        int c = lane + 32 * i;           // 64 float4 chunks per edge
        float4 v = xs[c];
        asm volatile("red.global.add.v4.f32 [%0], {%1, %2, %3, %4};"
                     :: "l"(Sd + c), "f"(v.x), "f"(v.y), "f"(v.z), "f"(v.w)
                     : "memory");
    }
}

// ---------------------------------------------------------------------------
// Build cat = [x, deg*x - S]   (pooled = deg*x - S)
// ---------------------------------------------------------------------------
__global__ void cat_kernel(const float* __restrict__ x) {
    int idx = blockIdx.x * blockDim.x + threadIdx.x;   // over N_NODES*64
    if (idx >= N_NODES * (H2 / 4)) return;
    int n = idx >> 6;      // node
    int c = idx & 63;      // float4 chunk within row
    float4 xv = ((const float4*)x)[idx];
    float4* cat4 = (float4*)g_cat;
    cat4[(size_t)n * 128 + c] = xv;
    float dg = (float)g_deg[n];
    float4 sv = ((const float4*)g_S)[idx];
    float4 pv = make_float4(dg * xv.x - sv.x, dg * xv.y - sv.y,
                            dg * xv.z - sv.z, dg * xv.w - sv.w);
    cat4[(size_t)n * 128 + 64 + c] = pv;
}

// ---------------------------------------------------------------------------
// tf32 tensor-core GEMM: C[M,N] = A[M,K] @ B[K,N] + bias, optional tanh.
// Block tile 128x128x32, 256 threads (8 warps), warp tile 32x64,
// mma.sync.aligned.m16n8k8.row.col.f32.tf32.tf32.f32.
// A stored k-major (transposed) in smem, B row-major; both padded +8 floats
// so fragment LDS banks = c*8 + r -> conflict-free.
// tf32 conversion applied once at STS time.
// ---------------------------------------------------------------------------
__device__ __forceinline__ unsigned f2tf32(float x) {
    unsigned r;
    asm("cvt.rna.tf32.f32 %0, %1;" : "=r"(r) : "f"(x));
    return r;
}

#define BM 128
#define BN 128
#define BK 32
#define LDA (BM + 8)   // 136
#define LDB (BN + 8)   // 136
#define SMEM_BYTES (2 * BK * LDA * 4 + 2 * BK * LDB * 4)   // 69632

template<int TANH>
__global__ __launch_bounds__(256)
void mma_gemm(const float* __restrict__ A, const float* __restrict__ B,
              const float* __restrict__ bias, float* __restrict__ C,
              int M, int N, int K)
{
    extern __shared__ float sm[];
    float* As = sm;                       // [2][BK][LDA]  (k-major)
    float* Bs = sm + 2 * BK * LDA;        // [2][BK][LDB]  (n-major)

    const int tid  = threadIdx.x;
    const int wid  = tid >> 5;
    const int lane = tid & 31;
    const int r = lane >> 2;              // groupID 0..7
    const int c = lane & 3;               // threadID_in_group 0..3
    const int warp_m = wid & 3, warp_n = wid >> 2;
    const int wm0 = warp_m * 32, wn0 = warp_n * 64;
    const int m0 = blockIdx.x * BM, n0 = blockIdx.y * BN;

    // global->smem load mappings
    const int am    = tid & 127;          // A: row within tile
    const int ak0   = tid >> 7;           // A: base k4 (0..1)
    const int brow  = tid >> 5;           // B: row 0..7
    const int bcol4 = lane * 4;           // B: col in floats (0..124)

    float acc[2][8][4];
#pragma unroll
    for (int i = 0; i < 2; ++i)
#pragma unroll
        for (int j = 0; j < 8; ++j)
#pragma unroll
            for (int q = 0; q < 4; ++q) acc[i][j][q] = 0.f;

    const int ntiles = K / BK;
    float4 aref[4], bref[4];

    auto loadA = [&](int kt) {
#pragma unroll
        for (int i = 0; i < 4; ++i) {
            int k4 = ak0 + 2 * i;         // 0..7
            int gm = m0 + am;
            if (gm < M)
                aref[i] = *(const float4*)(A + (size_t)gm * K + kt * BK + k4 * 4);
            else
                aref[i] = make_float4(0.f, 0.f, 0.f, 0.f);
        }
    };
    auto loadB = [&](int kt) {
#pragma unroll
        for (int i = 0; i < 4; ++i) {
            int row = brow + 8 * i;
            bref[i] = *(const float4*)(B + (size_t)(kt * BK + row) * N + n0 + bcol4);
        }
    };
    auto storeA = [&](int buf) {
        float* Ab = As + buf * BK * LDA;
#pragma unroll
        for (int i = 0; i < 4; ++i) {
            int k4 = ak0 + 2 * i;
            Ab[(k4 * 4 + 0) * LDA + am] = __uint_as_float(f2tf32(aref[i].x));
            Ab[(k4 * 4 + 1) * LDA + am] = __uint_as_float(f2tf32(aref[i].y));
            Ab[(k4 * 4 + 2) * LDA + am] = __uint_as_float(f2tf32(aref[i].z));
            Ab[(k4 * 4 + 3) * LDA + am] = __uint_as_float(f2tf32(aref[i].w));
        }
    };
    auto storeB = [&](int buf) {
        float* Bb = Bs + buf * BK * LDB;
#pragma unroll
        for (int i = 0; i < 4; ++i) {
            int row = brow + 8 * i;
            float4 t;
            t.x = __uint_as_float(f2tf32(bref[i].x));
            t.y = __uint_as_float(f2tf32(bref[i].y));
            t.z = __uint_as_float(f2tf32(bref[i].z));
            t.w = __uint_as_float(f2tf32(bref[i].w));
            *(float4*)(Bb + row * LDB + bcol4) = t;
        }
    };

    loadA(0); loadB(0);
    storeA(0); storeB(0);
    __syncthreads();

    for (int t = 0; t < ntiles; ++t) {
        int buf = t & 1;
        if (t + 1 < ntiles) { loadA(t + 1); loadB(t + 1); }

        const float* Ab = As + buf * BK * LDA;
        const float* Bb = Bs + buf * BK * LDB;

#pragma unroll
        for (int ks = 0; ks < BK / 8; ++ks) {
            int k = ks * 8;
            unsigned af[2][4];
#pragma unroll
            for (int mt = 0; mt < 2; ++mt) {
                int mrow = wm0 + mt * 16 + r;
                af[mt][0] = __float_as_uint(Ab[(k + c) * LDA + mrow]);
                af[mt][1] = __float_as_uint(Ab[(k + c) * LDA + mrow + 8]);
                af[mt][2] = __float_as_uint(Ab[(k + c + 4) * LDA + mrow]);
                af[mt][3] = __float_as_uint(Ab[(k + c + 4) * LDA + mrow + 8]);
            }
#pragma unroll
            for (int nt = 0; nt < 8; ++nt) {
                int ncol = wn0 + nt * 8 + r;
                unsigned b0 = __float_as_uint(Bb[(k + c) * LDB + ncol]);
                unsigned b1 = __float_as_uint(Bb[(k + c + 4) * LDB + ncol]);
#pragma unroll
                for (int mt = 0; mt < 2; ++mt) {
                    asm volatile(
                        "mma.sync.aligned.m16n8k8.row.col.f32.tf32.tf32.f32 "
                        "{%0,%1,%2,%3}, {%4,%5,%6,%7}, {%8,%9}, {%0,%1,%2,%3};"
                        : "+f"(acc[mt][nt][0]), "+f"(acc[mt][nt][1]),
                          "+f"(acc[mt][nt][2]), "+f"(acc[mt][nt][3])
                        : "r"(af[mt][0]), "r"(af[mt][1]),
                          "r"(af[mt][2]), "r"(af[mt][3]),
                          "r"(b0), "r"(b1));
                }
            }
        }
        if (t + 1 < ntiles) { storeA(1 - buf); storeB(1 - buf); }
        __syncthreads();
    }

    // Epilogue: c0,c1 -> row r; c2,c3 -> row r+8; cols 2c, 2c+1.
#pragma unroll
    for (int mt = 0; mt < 2; ++mt) {
#pragma unroll
        for (int half = 0; half < 2; ++half) {
            int gm = m0 + wm0 + mt * 16 + r + half * 8;
            if (gm >= M) continue;
#pragma unroll
            for (int nt = 0; nt < 8; ++nt) {
                int gn = n0 + wn0 + nt * 8 + 2 * c;
                float v0 = acc[mt][nt][half * 2 + 0] + bias[gn];
                float v1 = acc[mt][nt][half * 2 + 1] + bias[gn + 1];
                if (TANH) { v0 = tanhf(v0); v1 = tanhf(v1); }
                *(float2*)(C + (size_t)gm * N + gn) = make_float2(v0, v1);
            }
        }
    }
}

// ---------------------------------------------------------------------------
extern "C" void kernel_launch(void* const* d_in, const int* in_sizes, int n_in,
                              void* d_out, int out_size) {
    const float* x    = (const float*)d_in[0];   // node_feats [10000,256]
    const float* W1   = (const float*)d_in[1];   // [512,256]
    const float* b1   = (const float*)d_in[2];   // [256]
    const float* W2   = (const float*)d_in[3];   // [256,256]
    const float* b2   = (const float*)d_in[4];   // [256]
    const int*   esrc = (const int*)d_in[5];     // [320000]
    const int*   edst = (const int*)d_in[6];     // [320000]
    float*       out  = (float*)d_out;           // [10000,256]

    void *cat_p = nullptr, *h_p = nullptr;
    cudaGetSymbolAddress(&cat_p, g_cat);
    cudaGetSymbolAddress(&h_p, g_h);
    float* catf = (float*)cat_p;
    float* hf   = (float*)h_p;

    static bool attr_set = false;
    if (!attr_set) {
        cudaFuncSetAttribute(mma_gemm<0>,
                             cudaFuncAttributeMaxDynamicSharedMemorySize, SMEM_BYTES);
        cudaFuncSetAttribute(mma_gemm<1>,
                             cudaFuncAttributeMaxDynamicSharedMemorySize, SMEM_BYTES);
        attr_set = true;
    }

    // 1) zero scratch
    {
        int total = N_NODES * H2 / 4;
        zero_kernel<<<(total + 255) / 256, 256>>>();
    }
    // 2) edge scatter (deg + S)
    scatter_kernel<<<(N_EDGES * 32) / 256, 256>>>(x, esrc, edst);
    // 3) cat = [x, deg*x - S]
    cat_kernel<<<(N_NODES * 64 + 255) / 256, 256>>>(x);
    // 4) h = cat @ W1 + b1   (tf32 tensor cores)
    {
        dim3 grid((N_NODES + BM - 1) / BM, H2 / BN);
        mma_gemm<0><<<grid, 256, SMEM_BYTES>>>(catf, W1, b1, hf, N_NODES, H2, H4);
    }
    // 5) out = tanh(h @ W2 + b2)
    {
        dim3 grid((N_NODES + BM - 1) / BM, H2 / BN);
        mma_gemm<1><<<grid, 256, SMEM_BYTES>>>(hf, W2, b2, out, N_NODES, H2, H2);
    }
}

// round 5
// speedup vs baseline: 2.1321x; 1.4132x over previous
#include <cuda_runtime.h>
#include <math.h>

#define N_NODES 10000
#define N_EDGES 320000
#define H2 256          // node feature width
#define H4 512          // concat width
#define ELLW 128        // padded adjacency width (P(deg>128) ~ e^-40)

// Scratch (static __device__ arrays -- no allocation allowed)
__device__ int   g_ell[(size_t)N_NODES * ELLW]; // padded neighbor lists (src ids)
__device__ int   g_cur[N_NODES];                // per-node cursor == in-degree
__device__ float g_cat[(size_t)N_NODES * H4];   // [x, deg*x - S]
__device__ float g_h[N_NODES * H2];             // GEMM1 output

// ---------------------------------------------------------------------------
// Zero cursors
// ---------------------------------------------------------------------------
__global__ void zero_cur_kernel() {
    int idx = blockIdx.x * blockDim.x + threadIdx.x;
    if (idx < N_NODES) g_cur[idx] = 0;
}

// ---------------------------------------------------------------------------
// Fill padded adjacency: for each edge, append src to dst's list.
// ---------------------------------------------------------------------------
__global__ void fill_ell_kernel(const int* __restrict__ esrc,
                                const int* __restrict__ edst) {
    int e = blockIdx.x * blockDim.x + threadIdx.x;
    if (e >= N_EDGES) return;
    int s = esrc[e];
    int d = edst[e];
    int pos = atomicAdd(&g_cur[d], 1);
    if (pos < ELLW) g_ell[((size_t)d << 7) + pos] = s;
}

// ---------------------------------------------------------------------------
// Gather + cat: one warp per node.
//   S = sum_j x[src_j];  cat = [x, deg*x - S]
// Each lane owns float4 chunks {lane, lane+32} of the 64-chunk row.
// ---------------------------------------------------------------------------
__global__ __launch_bounds__(256)
void gather_cat_kernel(const float* __restrict__ x) {
    int gtid = blockIdx.x * blockDim.x + threadIdx.x;
    int node = gtid >> 5;
    int lane = gtid & 31;
    if (node >= N_NODES) return;

    const float4* x4 = (const float4*)x;
    int deg = g_cur[node];
    const int* __restrict__ nbr = g_ell + ((size_t)node << 7);

    float4 a0 = make_float4(0.f, 0.f, 0.f, 0.f);
    float4 a1 = make_float4(0.f, 0.f, 0.f, 0.f);

    int j = 0;
    for (; j + 2 <= deg; j += 2) {
        int s0 = nbr[j], s1 = nbr[j + 1];
        float4 v00 = x4[(size_t)s0 * 64 + lane];
        float4 v01 = x4[(size_t)s0 * 64 + lane + 32];
        float4 v10 = x4[(size_t)s1 * 64 + lane];
        float4 v11 = x4[(size_t)s1 * 64 + lane + 32];
        a0.x += v00.x; a0.y += v00.y; a0.z += v00.z; a0.w += v00.w;
        a1.x += v01.x; a1.y += v01.y; a1.z += v01.z; a1.w += v01.w;
        a0.x += v10.x; a0.y += v10.y; a0.z += v10.z; a0.w += v10.w;
        a1.x += v11.x; a1.y += v11.y; a1.z += v11.z; a1.w += v11.w;
    }
    if (j < deg) {
        int s0 = nbr[j];
        float4 v00 = x4[(size_t)s0 * 64 + lane];
        float4 v01 = x4[(size_t)s0 * 64 + lane + 32];
        a0.x += v00.x; a0.y += v00.y; a0.z += v00.z; a0.w += v00.w;
        a1.x += v01.x; a1.y += v01.y; a1.z += v01.z; a1.w += v01.w;
    }

    float dg = (float)deg;
    float4 xv0 = x4[(size_t)node * 64 + lane];
    float4 xv1 = x4[(size_t)node * 64 + lane + 32];
    float4* cat4 = (float4*)g_cat;
    size_t crow = (size_t)node * 128;
    cat4[crow + lane]      = xv0;
    cat4[crow + 32 + lane] = xv1;
    cat4[crow + 64 + lane] = make_float4(dg * xv0.x - a0.x, dg * xv0.y - a0.y,
                                         dg * xv0.z - a0.z, dg * xv0.w - a0.w);
    cat4[crow + 96 + lane] = make_float4(dg * xv1.x - a1.x, dg * xv1.y - a1.y,
                                         dg * xv1.z - a1.z, dg * xv1.w - a1.w);
}

// ---------------------------------------------------------------------------
// tf32 tensor-core GEMM: C[M,N] = A[M,K] @ B[K,N] + bias, optional tanh.
// Block tile 128x64x32, 256 threads (8 warps, 4x2), warp tile 32x32.
// mma.sync.aligned.m16n8k8.row.col.f32.tf32.tf32.f32.
// A k-major in smem, B n-major; pads give conflict-free fragment LDS.
// ---------------------------------------------------------------------------
__device__ __forceinline__ unsigned f2tf32(float x) {
    unsigned r;
    asm("cvt.rna.tf32.f32 %0, %1;" : "=r"(r) : "f"(x));
    return r;
}

#define BM 128
#define BN 64
#define BK 32
#define LDA (BM + 8)   // 136
#define LDB (BN + 8)   // 72
#define SMEM_BYTES (2 * BK * LDA * 4 + 2 * BK * LDB * 4)   // 53248

template<int TANH>
__global__ __launch_bounds__(256, 2)
void mma_gemm(const float* __restrict__ A, const float* __restrict__ B,
              const float* __restrict__ bias, float* __restrict__ C,
              int M, int N, int K)
{
    extern __shared__ float sm[];
    float* As = sm;                       // [2][BK][LDA]  (k-major)
    float* Bs = sm + 2 * BK * LDA;        // [2][BK][LDB]  (n-major)

    const int tid  = threadIdx.x;
    const int wid  = tid >> 5;
    const int lane = tid & 31;
    const int r = lane >> 2;              // groupID 0..7
    const int c = lane & 3;               // threadID_in_group 0..3
    const int wm0 = (wid & 3) * 32;
    const int wn0 = (wid >> 2) * 32;
    const int m0 = blockIdx.x * BM, n0 = blockIdx.y * BN;

    // A: 128 rows x 8 float4 segs; thread -> row tid>>1, segs (tid&1)*4 + i
    const int arow = tid >> 1;
    const int aseg0 = (tid & 1) * 4;
    // B: 32 rows x 16 float4; thread -> row tid>>3, cols (tid&7)*8 (+4)
    const int brow = tid >> 3;
    const int bcol = (tid & 7) * 8;

    float acc[2][4][4];
#pragma unroll
    for (int i = 0; i < 2; ++i)
#pragma unroll
        for (int j = 0; j < 4; ++j)
#pragma unroll
            for (int q = 0; q < 4; ++q) acc[i][j][q] = 0.f;

    const int ntiles = K / BK;
    float4 aref[4], bref[2];

    auto loadA = [&](int kt) {
        int gm = m0 + arow;
#pragma unroll
        for (int i = 0; i < 4; ++i) {
            if (gm < M)
                aref[i] = *(const float4*)(A + (size_t)gm * K + kt * BK + (aseg0 + i) * 4);
            else
                aref[i] = make_float4(0.f, 0.f, 0.f, 0.f);
        }
    };
    auto loadB = [&](int kt) {
        const float* Brow = B + (size_t)(kt * BK + brow) * N + n0 + bcol;
        bref[0] = *(const float4*)Brow;
        bref[1] = *(const float4*)(Brow + 4);
    };
    auto storeA = [&](int buf) {
        float* Ab = As + buf * BK * LDA;
#pragma unroll
        for (int i = 0; i < 4; ++i) {
            int k4 = aseg0 + i;
            Ab[(k4 * 4 + 0) * LDA + arow] = __uint_as_float(f2tf32(aref[i].x));
            Ab[(k4 * 4 + 1) * LDA + arow] = __uint_as_float(f2tf32(aref[i].y));
            Ab[(k4 * 4 + 2) * LDA + arow] = __uint_as_float(f2tf32(aref[i].z));
            Ab[(k4 * 4 + 3) * LDA + arow] = __uint_as_float(f2tf32(aref[i].w));
        }
    };
    auto storeB = [&](int buf) {
        float* Bb = Bs + buf * BK * LDB + brow * LDB + bcol;
#pragma unroll
        for (int i = 0; i < 2; ++i) {
            float4 t;
            t.x = __uint_as_float(f2tf32(bref[i].x));
            t.y = __uint_as_float(f2tf32(bref[i].y));
            t.z = __uint_as_float(f2tf32(bref[i].z));
            t.w = __uint_as_float(f2tf32(bref[i].w));
            *(float4*)(Bb + i * 4) = t;
        }
    };

    loadA(0); loadB(0);
    storeA(0); storeB(0);
    __syncthreads();

    for (int t = 0; t < ntiles; ++t) {
        int buf = t & 1;
        if (t + 1 < ntiles) { loadA(t + 1); loadB(t + 1); }

        const float* Ab = As + buf * BK * LDA;
        const float* Bb = Bs + buf * BK * LDB;

#pragma unroll
        for (int ks = 0; ks < BK / 8; ++ks) {
            int k = ks * 8;
            unsigned af[2][4];
#pragma unroll
            for (int mt = 0; mt < 2; ++mt) {
                int mrow = wm0 + mt * 16 + r;
                af[mt][0] = __float_as_uint(Ab[(k + c) * LDA + mrow]);
                af[mt][1] = __float_as_uint(Ab[(k + c) * LDA + mrow + 8]);
                af[mt][2] = __float_as_uint(Ab[(k + c + 4) * LDA + mrow]);
                af[mt][3] = __float_as_uint(Ab[(k + c + 4) * LDA + mrow + 8]);
            }
#pragma unroll
            for (int nt = 0; nt < 4; ++nt) {
                int ncol = wn0 + nt * 8 + r;
                unsigned b0 = __float_as_uint(Bb[(k + c) * LDB + ncol]);
                unsigned b1 = __float_as_uint(Bb[(k + c + 4) * LDB + ncol]);
#pragma unroll
                for (int mt = 0; mt < 2; ++mt) {
                    asm volatile(
                        "mma.sync.aligned.m16n8k8.row.col.f32.tf32.tf32.f32 "
                        "{%0,%1,%2,%3}, {%4,%5,%6,%7}, {%8,%9}, {%0,%1,%2,%3};"
                        : "+f"(acc[mt][nt][0]), "+f"(acc[mt][nt][1]),
                          "+f"(acc[mt][nt][2]), "+f"(acc[mt][nt][3])
                        : "r"(af[mt][0]), "r"(af[mt][1]),
                          "r"(af[mt][2]), "r"(af[mt][3]),
                          "r"(b0), "r"(b1));
                }
            }
        }
        if (t + 1 < ntiles) { storeA(1 - buf); storeB(1 - buf); }
        __syncthreads();
    }

    // Epilogue: c0,c1 -> row r; c2,c3 -> row r+8; cols 2c, 2c+1.
#pragma unroll
    for (int mt = 0; mt < 2; ++mt) {
#pragma unroll
        for (int half = 0; half < 2; ++half) {
            int gm = m0 + wm0 + mt * 16 + r + half * 8;
            if (gm >= M) continue;
#pragma unroll
            for (int nt = 0; nt < 4; ++nt) {
                int gn = n0 + wn0 + nt * 8 + 2 * c;
                float v0 = acc[mt][nt][half * 2 + 0] + bias[gn];
                float v1 = acc[mt][nt][half * 2 + 1] + bias[gn + 1];
                if (TANH) { v0 = tanhf(v0); v1 = tanhf(v1); }
                *(float2*)(C + (size_t)gm * N + gn) = make_float2(v0, v1);
            }
        }
    }
}

// ---------------------------------------------------------------------------
extern "C" void kernel_launch(void* const* d_in, const int* in_sizes, int n_in,
                              void* d_out, int out_size) {
    const float* x    = (const float*)d_in[0];   // node_feats [10000,256]
    const float* W1   = (const float*)d_in[1];   // [512,256]
    const float* b1   = (const float*)d_in[2];   // [256]
    const float* W2   = (const float*)d_in[3];   // [256,256]
    const float* b2   = (const float*)d_in[4];   // [256]
    const int*   esrc = (const int*)d_in[5];     // [320000]
    const int*   edst = (const int*)d_in[6];     // [320000]
    float*       out  = (float*)d_out;           // [10000,256]

    void *cat_p = nullptr, *h_p = nullptr;
    cudaGetSymbolAddress(&cat_p, g_cat);
    cudaGetSymbolAddress(&h_p, g_h);
    float* catf = (float*)cat_p;
    float* hf   = (float*)h_p;

    static bool attr_set = false;
    if (!attr_set) {
        cudaFuncSetAttribute(mma_gemm<0>,
                             cudaFuncAttributeMaxDynamicSharedMemorySize, SMEM_BYTES);
        cudaFuncSetAttribute(mma_gemm<1>,
                             cudaFuncAttributeMaxDynamicSharedMemorySize, SMEM_BYTES);
        attr_set = true;
    }

    // 1) zero cursors
    zero_cur_kernel<<<(N_NODES + 255) / 256, 256>>>();
    // 2) build padded adjacency
    fill_ell_kernel<<<(N_EDGES + 255) / 256, 256>>>(esrc, edst);
    // 3) gather + cat  (one warp per node)
    gather_cat_kernel<<<(N_NODES * 32 + 255) / 256, 256>>>(x);
    // 4) h = cat @ W1 + b1   (tf32 tensor cores)
    {
        dim3 grid((N_NODES + BM - 1) / BM, H2 / BN);
        mma_gemm<0><<<grid, 256, SMEM_BYTES>>>(catf, W1, b1, hf, N_NODES, H2, H4);
    }
    // 5) out = tanh(h @ W2 + b2)
    {
        dim3 grid((N_NODES + BM - 1) / BM, H2 / BN);
        mma_gemm<1><<<grid, 256, SMEM_BYTES>>>(hf, W2, b2, out, N_NODES, H2, H2);
    }
}

// round 7
// speedup vs baseline: 2.7290x; 1.2800x over previous
#include <cuda_runtime.h>
#include <math.h>
#include <stdint.h>

#define N_NODES 10000
#define N_EDGES 320000
#define H2 256          // node feature width
#define H4 512          // concat width
#define ELLW 128        // padded adjacency width

// Scratch (static __device__ arrays -- no allocation allowed)
__device__ int   g_ell[(size_t)N_NODES * ELLW];
__device__ int   g_cur[N_NODES];
__device__ float g_cat[(size_t)N_NODES * H4];
__device__ float g_h[N_NODES * H2];

// ---------------------------------------------------------------------------
// Graph preprocessing (unchanged -- near L2-traffic floor)
// ---------------------------------------------------------------------------
__global__ void zero_cur_kernel() {
    int idx = blockIdx.x * blockDim.x + threadIdx.x;
    if (idx < N_NODES) g_cur[idx] = 0;
}

__global__ void fill_ell_kernel(const int* __restrict__ esrc,
                                const int* __restrict__ edst) {
    int e = blockIdx.x * blockDim.x + threadIdx.x;
    if (e >= N_EDGES) return;
    int s = esrc[e];
    int d = edst[e];
    int pos = atomicAdd(&g_cur[d], 1);
    if (pos < ELLW) g_ell[((size_t)d << 7) + pos] = s;
}

__global__ __launch_bounds__(256)
void gather_cat_kernel(const float* __restrict__ x) {
    int gtid = blockIdx.x * blockDim.x + threadIdx.x;
    int node = gtid >> 5;
    int lane = gtid & 31;
    if (node >= N_NODES) return;

    const float4* x4 = (const float4*)x;
    int deg = g_cur[node];
    const int* __restrict__ nbr = g_ell + ((size_t)node << 7);

    float4 a0 = make_float4(0.f, 0.f, 0.f, 0.f);
    float4 a1 = make_float4(0.f, 0.f, 0.f, 0.f);

    int j = 0;
    for (; j + 2 <= deg; j += 2) {
        int s0 = nbr[j], s1 = nbr[j + 1];
        float4 v00 = x4[(size_t)s0 * 64 + lane];
        float4 v01 = x4[(size_t)s0 * 64 + lane + 32];
        float4 v10 = x4[(size_t)s1 * 64 + lane];
        float4 v11 = x4[(size_t)s1 * 64 + lane + 32];
        a0.x += v00.x; a0.y += v00.y; a0.z += v00.z; a0.w += v00.w;
        a1.x += v01.x; a1.y += v01.y; a1.z += v01.z; a1.w += v01.w;
        a0.x += v10.x; a0.y += v10.y; a0.z += v10.z; a0.w += v10.w;
        a1.x += v11.x; a1.y += v11.y; a1.z += v11.z; a1.w += v11.w;
    }
    if (j < deg) {
        int s0 = nbr[j];
        float4 v00 = x4[(size_t)s0 * 64 + lane];
        float4 v01 = x4[(size_t)s0 * 64 + lane + 32];
        a0.x += v00.x; a0.y += v00.y; a0.z += v00.z; a0.w += v00.w;
        a1.x += v01.x; a1.y += v01.y; a1.z += v01.z; a1.w += v01.w;
    }

    float dg = (float)deg;
    float4 xv0 = x4[(size_t)node * 64 + lane];
    float4 xv1 = x4[(size_t)node * 64 + lane + 32];
    float4* cat4 = (float4*)g_cat;
    size_t crow = (size_t)node * 128;
    cat4[crow + lane]      = xv0;
    cat4[crow + 32 + lane] = xv1;
    cat4[crow + 64 + lane] = make_float4(dg * xv0.x - a0.x, dg * xv0.y - a0.y,
                                         dg * xv0.z - a0.z, dg * xv0.w - a0.w);
    cat4[crow + 96 + lane] = make_float4(dg * xv1.x - a1.x, dg * xv1.y - a1.y,
                                         dg * xv1.z - a1.z, dg * xv1.w - a1.w);
}

// ---------------------------------------------------------------------------
// tf32 mma.sync GEMM with cp.async pipeline.
//   C[M,N] = A[M,K] @ B[K,N] + bias (+tanh)
// Block tile 128x64x32, 256 threads (8 warps, 4x2), warp tile 32x32.
// A smem: m-major raw fp32, row pad 36 floats -> fragment LDS bank = 4r+c,
// conflict-free. B smem: n-major, row pad 72. tf32 cvt.rna after fragment LDS.
// 2-stage cp.async double buffer; __launch_bounds__(256,3) for 24 warps/SM.
// ---------------------------------------------------------------------------
__device__ __forceinline__ unsigned f2tf32(float x) {
    unsigned r;
    asm("cvt.rna.tf32.f32 %0, %1;" : "=r"(r) : "f"(x));
    return r;
}
__device__ __forceinline__ void cp16(uint32_t dst, const void* src, int srcsz) {
    asm volatile("cp.async.cg.shared.global [%0], [%1], 16, %2;"
                 :: "r"(dst), "l"(src), "r"(srcsz) : "memory");
}
#define CP_COMMIT() asm volatile("cp.async.commit_group;" ::: "memory")
#define CP_WAIT(n)  asm volatile("cp.async.wait_group %0;" :: "n"(n) : "memory")

#define BM 128
#define BN 64
#define BK 32
#define LDKA 36                       // A smem row length in floats (144B)
#define LDBS 72                       // B smem row length in floats (288B)
#define A_STAGE (BM * LDKA)           // 4608 floats
#define B_STAGE (BK * LDBS)           // 2304 floats
#define SMEM_BYTES ((2 * (A_STAGE + B_STAGE)) * 4)   // 55296 B

template<int TANH>
__global__ __launch_bounds__(256, 3)
void mma_gemm(const float* __restrict__ A, const float* __restrict__ B,
              const float* __restrict__ bias, float* __restrict__ C,
              int M, int N, int K)
{
    extern __shared__ float sm[];
    float* Asm = sm;                          // [2][BM][LDKA]
    float* Bsm = sm + 2 * A_STAGE;            // [2][BK][LDBS]
    uint32_t a_sa = (uint32_t)__cvta_generic_to_shared(Asm);
    uint32_t b_sa = (uint32_t)__cvta_generic_to_shared(Bsm);

    const int tid  = threadIdx.x;
    const int wid  = tid >> 5;
    const int lane = tid & 31;
    const int r = lane >> 2;              // groupID 0..7
    const int c = lane & 3;               // threadID_in_group 0..3
    const int wm0 = (wid & 3) * 32;
    const int wn0 = (wid >> 2) * 32;
    const int m0 = blockIdx.x * BM, n0 = blockIdx.y * BN;

    float acc[2][4][4];
#pragma unroll
    for (int i = 0; i < 2; ++i)
#pragma unroll
        for (int j = 0; j < 4; ++j)
#pragma unroll
            for (int q = 0; q < 4; ++q) acc[i][j][q] = 0.f;

    const int T = K / BK;

    // cp.async mappings:
    // A: 128 rows x 8 x 16B chunks = 1024 chunks, 4 per thread
    // B: 32 rows x 16 x 16B chunks = 512 chunks, 2 per thread
    auto prefetch = [&](int t, int buf) {
        uint32_t ab = a_sa + (uint32_t)buf * A_STAGE * 4;
        const float* Ap = A + (size_t)t * BK;
#pragma unroll
        for (int i = 0; i < 4; ++i) {
            int ch  = tid + 256 * i;
            int row = ch >> 3, seg = ch & 7;
            int gm  = m0 + row;
            cp16(ab + row * (LDKA * 4) + seg * 16,
                 Ap + (size_t)gm * K + seg * 4, gm < M ? 16 : 0);
        }
        uint32_t bb = b_sa + (uint32_t)buf * B_STAGE * 4;
        const float* Bp = B + (size_t)t * BK * N + n0;
#pragma unroll
        for (int i = 0; i < 2; ++i) {
            int ch  = tid + 256 * i;
            int row = ch >> 4, seg = ch & 15;
            cp16(bb + row * (LDBS * 4) + seg * 16,
                 Bp + (size_t)row * N + seg * 4, 16);
        }
        CP_COMMIT();
    };

    prefetch(0, 0);

    for (int t = 0; t < T; ++t) {
        int buf = t & 1;
        if (t + 1 < T) {
            prefetch(t + 1, 1 - buf);
            CP_WAIT(1);
        } else {
            CP_WAIT(0);
        }
        __syncthreads();

        const float* Ab = Asm + buf * A_STAGE;
        const float* Bb = Bsm + buf * B_STAGE;

#pragma unroll
        for (int kt = 0; kt < 4; ++kt) {
            int k = kt * 8;
            unsigned af[2][4];
#pragma unroll
            for (int mt = 0; mt < 2; ++mt) {
                int row = wm0 + mt * 16 + r;
                af[mt][0] = f2tf32(Ab[row * LDKA + k + c]);
                af[mt][1] = f2tf32(Ab[(row + 8) * LDKA + k + c]);
                af[mt][2] = f2tf32(Ab[row * LDKA + k + c + 4]);
                af[mt][3] = f2tf32(Ab[(row + 8) * LDKA + k + c + 4]);
            }
#pragma unroll
            for (int nt = 0; nt < 4; ++nt) {
                int ncol = wn0 + nt * 8 + r;
                unsigned b0 = f2tf32(Bb[(k + c) * LDBS + ncol]);
                unsigned b1 = f2tf32(Bb[(k + c + 4) * LDBS + ncol]);
#pragma unroll
                for (int mt = 0; mt < 2; ++mt) {
                    asm volatile(
                        "mma.sync.aligned.m16n8k8.row.col.f32.tf32.tf32.f32 "
                        "{%0,%1,%2,%3}, {%4,%5,%6,%7}, {%8,%9}, {%0,%1,%2,%3};"
                        : "+f"(acc[mt][nt][0]), "+f"(acc[mt][nt][1]),
                          "+f"(acc[mt][nt][2]), "+f"(acc[mt][nt][3])
                        : "r"(af[mt][0]), "r"(af[mt][1]),
                          "r"(af[mt][2]), "r"(af[mt][3]),
                          "r"(b0), "r"(b1));
                }
            }
        }
        __syncthreads();
    }

    // Epilogue: c0,c1 -> row r; c2,c3 -> row r+8; cols 2c, 2c+1.
#pragma unroll
    for (int mt = 0; mt < 2; ++mt) {
#pragma unroll
        for (int half = 0; half < 2; ++half) {
            int gm = m0 + wm0 + mt * 16 + r + half * 8;
            if (gm >= M) continue;
#pragma unroll
            for (int nt = 0; nt < 4; ++nt) {
                int gn = n0 + wn0 + nt * 8 + 2 * c;
                float v0 = acc[mt][nt][half * 2 + 0] + bias[gn];
                float v1 = acc[mt][nt][half * 2 + 1] + bias[gn + 1];
                if (TANH) { v0 = tanhf(v0); v1 = tanhf(v1); }
                *(float2*)(C + (size_t)gm * N + gn) = make_float2(v0, v1);
            }
        }
    }
}

// ---------------------------------------------------------------------------
extern "C" void kernel_launch(void* const* d_in, const int* in_sizes, int n_in,
                              void* d_out, int out_size) {
    const float* x    = (const float*)d_in[0];   // node_feats [10000,256]
    const float* W1   = (const float*)d_in[1];   // [512,256]
    const float* b1   = (const float*)d_in[2];   // [256]
    const float* W2   = (const float*)d_in[3];   // [256,256]
    const float* b2   = (const float*)d_in[4];   // [256]
    const int*   esrc = (const int*)d_in[5];     // [320000]
    const int*   edst = (const int*)d_in[6];     // [320000]
    float*       out  = (float*)d_out;           // [10000,256]

    void *cat_p = nullptr, *h_p = nullptr;
    cudaGetSymbolAddress(&cat_p, g_cat);
    cudaGetSymbolAddress(&h_p, g_h);
    float* catf = (float*)cat_p;
    float* hf   = (float*)h_p;

    static bool attr_set = false;
    if (!attr_set) {
        cudaFuncSetAttribute(mma_gemm<0>,
                             cudaFuncAttributeMaxDynamicSharedMemorySize, SMEM_BYTES);
        cudaFuncSetAttribute(mma_gemm<1>,
                             cudaFuncAttributeMaxDynamicSharedMemorySize, SMEM_BYTES);
        attr_set = true;
    }

    // 1) zero cursors
    zero_cur_kernel<<<(N_NODES + 255) / 256, 256>>>();
    // 2) build padded adjacency
    fill_ell_kernel<<<(N_EDGES + 255) / 256, 256>>>(esrc, edst);
    // 3) gather + cat  (one warp per node)
    gather_cat_kernel<<<(N_NODES * 32 + 255) / 256, 256>>>(x);
    // 4) h = cat @ W1 + b1   (tf32 mma.sync + cp.async)
    {
        dim3 grid((N_NODES + BM - 1) / BM, H2 / BN);
        mma_gemm<0><<<grid, 256, SMEM_BYTES>>>(catf, W1, b1, hf, N_NODES, H2, H4);
    }
    // 5) out = tanh(h @ W2 + b2)
    {
        dim3 grid((N_NODES + BM - 1) / BM, H2 / BN);
        mma_gemm<1><<<grid, 256, SMEM_BYTES>>>(hf, W2, b2, out, N_NODES, H2, H2);
    }
}

// round 9
// speedup vs baseline: 2.9508x; 1.0812x over previous
#include <cuda_runtime.h>
#include <math.h>
#include <stdint.h>

#define N_NODES 10000
#define N_EDGES 320000
#define H2 256          // node feature width
#define H4 512          // concat width
#define ELLW 128        // padded adjacency width

// Scratch (static __device__ arrays -- no allocation allowed)
__device__ int   g_ell[(size_t)N_NODES * ELLW];
__device__ int   g_cur[N_NODES];
__device__ float g_cat[(size_t)N_NODES * H4];   // tf32-rounded
__device__ float g_h[N_NODES * H2];             // tf32-rounded
__device__ float g_w1r[H4 * H2];                // tf32-rounded W1
__device__ float g_w2r[H2 * H2];                // tf32-rounded W2

__device__ __forceinline__ unsigned f2tf32(float x) {
    unsigned r;
    asm("cvt.rna.tf32.f32 %0, %1;" : "=r"(r) : "f"(x));
    return r;
}
__device__ __forceinline__ float f2tf32f(float x) {
    return __uint_as_float(f2tf32(x));
}

// ---------------------------------------------------------------------------
// Preprocessing
// ---------------------------------------------------------------------------
__global__ void zero_cur_kernel() {
    int idx = blockIdx.x * blockDim.x + threadIdx.x;
    if (idx < N_NODES) g_cur[idx] = 0;
}

// Round W1, W2 to tf32 once (removes cvt from GEMM mainloops)
__global__ void round_w_kernel(const float* __restrict__ W1,
                               const float* __restrict__ W2) {
    int idx = blockIdx.x * blockDim.x + threadIdx.x;
    const int n1 = H4 * H2, n2 = H2 * H2;
    if (idx < n1) g_w1r[idx] = f2tf32f(W1[idx]);
    if (idx < n2) g_w2r[idx] = f2tf32f(W2[idx]);
}

__global__ void fill_ell_kernel(const int* __restrict__ esrc,
                                const int* __restrict__ edst) {
    int e = blockIdx.x * blockDim.x + threadIdx.x;
    if (e >= N_EDGES) return;
    int s = esrc[e];
    int d = edst[e];
    int pos = atomicAdd(&g_cur[d], 1);
    if (pos < ELLW) g_ell[((size_t)d << 7) + pos] = s;
}

// Gather + cat, writing tf32-rounded values.
__global__ __launch_bounds__(256)
void gather_cat_kernel(const float* __restrict__ x) {
    int gtid = blockIdx.x * blockDim.x + threadIdx.x;
    int node = gtid >> 5;
    int lane = gtid & 31;
    if (node >= N_NODES) return;

    const float4* x4 = (const float4*)x;
    int deg = g_cur[node];
    const int* __restrict__ nbr = g_ell + ((size_t)node << 7);

    float4 a0 = make_float4(0.f, 0.f, 0.f, 0.f);
    float4 a1 = make_float4(0.f, 0.f, 0.f, 0.f);

    int j = 0;
    for (; j + 2 <= deg; j += 2) {
        int s0 = nbr[j], s1 = nbr[j + 1];
        float4 v00 = x4[(size_t)s0 * 64 + lane];
        float4 v01 = x4[(size_t)s0 * 64 + lane + 32];
        float4 v10 = x4[(size_t)s1 * 64 + lane];
        float4 v11 = x4[(size_t)s1 * 64 + lane + 32];
        a0.x += v00.x; a0.y += v00.y; a0.z += v00.z; a0.w += v00.w;
        a1.x += v01.x; a1.y += v01.y; a1.z += v01.z; a1.w += v01.w;
        a0.x += v10.x; a0.y += v10.y; a0.z += v10.z; a0.w += v10.w;
        a1.x += v11.x; a1.y += v11.y; a1.z += v11.z; a1.w += v11.w;
    }
    if (j < deg) {
        int s0 = nbr[j];
        float4 v00 = x4[(size_t)s0 * 64 + lane];
        float4 v01 = x4[(size_t)s0 * 64 + lane + 32];
        a0.x += v00.x; a0.y += v00.y; a0.z += v00.z; a0.w += v00.w;
        a1.x += v01.x; a1.y += v01.y; a1.z += v01.z; a1.w += v01.w;
    }

    float dg = (float)deg;
    float4 xv0 = x4[(size_t)node * 64 + lane];
    float4 xv1 = x4[(size_t)node * 64 + lane + 32];
    float4* cat4 = (float4*)g_cat;
    size_t crow = (size_t)node * 128;
    cat4[crow + lane] = make_float4(f2tf32f(xv0.x), f2tf32f(xv0.y),
                                    f2tf32f(xv0.z), f2tf32f(xv0.w));
    cat4[crow + 32 + lane] = make_float4(f2tf32f(xv1.x), f2tf32f(xv1.y),
                                         f2tf32f(xv1.z), f2tf32f(xv1.w));
    cat4[crow + 64 + lane] = make_float4(f2tf32f(dg * xv0.x - a0.x),
                                         f2tf32f(dg * xv0.y - a0.y),
                                         f2tf32f(dg * xv0.z - a0.z),
                                         f2tf32f(dg * xv0.w - a0.w));
    cat4[crow + 96 + lane] = make_float4(f2tf32f(dg * xv1.x - a1.x),
                                         f2tf32f(dg * xv1.y - a1.y),
                                         f2tf32f(dg * xv1.z - a1.z),
                                         f2tf32f(dg * xv1.w - a1.w));
}

// ---------------------------------------------------------------------------
// tf32 mma.sync GEMM, cp.async pipeline, pre-rounded operands (no mainloop cvt)
//   C[M,N] = A[M,K] @ B[K,N] + bias (+tanh / +tf32-round)
// Block tile 64x64x32, 128 threads (4 warps, 2x2), warp tile 32x32.
// A smem m-major pad 36, B smem n-major pad 72 -> conflict-free fragment LDS.
// ---------------------------------------------------------------------------
__device__ __forceinline__ void cp16(uint32_t dst, const void* src, int srcsz) {
    asm volatile("cp.async.cg.shared.global [%0], [%1], 16, %2;"
                 :: "r"(dst), "l"(src), "r"(srcsz) : "memory");
}
#define CP_COMMIT() asm volatile("cp.async.commit_group;" ::: "memory")
#define CP_WAIT(n)  asm volatile("cp.async.wait_group %0;" :: "n"(n) : "memory")

#define BM 64
#define BN 64
#define BK 32
#define LDKA 36                       // A smem row floats
#define LDBS 72                       // B smem row floats
#define A_STAGE (BM * LDKA)           // 2304 floats
#define B_STAGE (BK * LDBS)           // 2304 floats
#define SMEM_BYTES ((2 * (A_STAGE + B_STAGE)) * 4)   // 36864 B

// TANH: 0 = round-to-tf32 epilogue (GEMM1), 1 = tanh epilogue (GEMM2)
template<int TANH>
__global__ __launch_bounds__(128, 5)
void mma_gemm(const float* __restrict__ A, const float* __restrict__ B,
              const float* __restrict__ bias, float* __restrict__ C,
              int M, int N, int K)
{
    extern __shared__ float sm[];
    float* Asm = sm;                          // [2][BM][LDKA]
    float* Bsm = sm + 2 * A_STAGE;            // [2][BK][LDBS]
    uint32_t a_sa = (uint32_t)__cvta_generic_to_shared(Asm);
    uint32_t b_sa = (uint32_t)__cvta_generic_to_shared(Bsm);

    const int tid  = threadIdx.x;
    const int wid  = tid >> 5;
    const int lane = tid & 31;
    const int r = lane >> 2;
    const int c = lane & 3;
    const int wm0 = (wid & 1) * 32;
    const int wn0 = (wid >> 1) * 32;
    const int m0 = blockIdx.x * BM, n0 = blockIdx.y * BN;

    float acc[2][4][4];
#pragma unroll
    for (int i = 0; i < 2; ++i)
#pragma unroll
        for (int j = 0; j < 4; ++j)
#pragma unroll
            for (int q = 0; q < 4; ++q) acc[i][j][q] = 0.f;

    const int T = K / BK;

    // cp.async mappings (128 threads):
    // A: 64 rows x 8 chunks = 512 chunks, 4/thread
    // B: 32 rows x 16 chunks = 512 chunks, 4/thread
    auto prefetch = [&](int t, int buf) {
        uint32_t ab = a_sa + (uint32_t)buf * A_STAGE * 4;
        const float* Ap = A + (size_t)t * BK;
#pragma unroll
        for (int i = 0; i < 4; ++i) {
            int ch  = tid + 128 * i;
            int row = ch >> 3, seg = ch & 7;
            int gm  = m0 + row;
            cp16(ab + row * (LDKA * 4) + seg * 16,
                 Ap + (size_t)gm * K + seg * 4, gm < M ? 16 : 0);
        }
        uint32_t bb = b_sa + (uint32_t)buf * B_STAGE * 4;
        const float* Bp = B + (size_t)t * BK * N + n0;
#pragma unroll
        for (int i = 0; i < 4; ++i) {
            int ch  = tid + 128 * i;
            int row = ch >> 4, seg = ch & 15;
            cp16(bb + row * (LDBS * 4) + seg * 16,
                 Bp + (size_t)row * N + seg * 4, 16);
        }
        CP_COMMIT();
    };

    prefetch(0, 0);

    for (int t = 0; t < T; ++t) {
        int buf = t & 1;
        if (t + 1 < T) {
            prefetch(t + 1, 1 - buf);
            CP_WAIT(1);
        } else {
            CP_WAIT(0);
        }
        __syncthreads();

        const float* Ab = Asm + buf * A_STAGE;
        const float* Bb = Bsm + buf * B_STAGE;

#pragma unroll
        for (int kt = 0; kt < 4; ++kt) {
            int k = kt * 8;
            unsigned af[2][4];
#pragma unroll
            for (int mt = 0; mt < 2; ++mt) {
                int row = wm0 + mt * 16 + r;
                af[mt][0] = __float_as_uint(Ab[row * LDKA + k + c]);
                af[mt][1] = __float_as_uint(Ab[(row + 8) * LDKA + k + c]);
                af[mt][2] = __float_as_uint(Ab[row * LDKA + k + c + 4]);
                af[mt][3] = __float_as_uint(Ab[(row + 8) * LDKA + k + c + 4]);
            }
#pragma unroll
            for (int nt = 0; nt < 4; ++nt) {
                int ncol = wn0 + nt * 8 + r;
                unsigned b0 = __float_as_uint(Bb[(k + c) * LDBS + ncol]);
                unsigned b1 = __float_as_uint(Bb[(k + c + 4) * LDBS + ncol]);
#pragma unroll
                for (int mt = 0; mt < 2; ++mt) {
                    asm volatile(
                        "mma.sync.aligned.m16n8k8.row.col.f32.tf32.tf32.f32 "
                        "{%0,%1,%2,%3}, {%4,%5,%6,%7}, {%8,%9}, {%0,%1,%2,%3};"
                        : "+f"(acc[mt][nt][0]), "+f"(acc[mt][nt][1]),
                          "+f"(acc[mt][nt][2]), "+f"(acc[mt][nt][3])
                        : "r"(af[mt][0]), "r"(af[mt][1]),
                          "r"(af[mt][2]), "r"(af[mt][3]),
                          "r"(b0), "r"(b1));
                }
            }
        }
        __syncthreads();
    }

    // Epilogue: c0,c1 -> row r; c2,c3 -> row r+8; cols 2c, 2c+1.
#pragma unroll
    for (int mt = 0; mt < 2; ++mt) {
#pragma unroll
        for (int half = 0; half < 2; ++half) {
            int gm = m0 + wm0 + mt * 16 + r + half * 8;
            if (gm >= M) continue;
#pragma unroll
            for (int nt = 0; nt < 4; ++nt) {
                int gn = n0 + wn0 + nt * 8 + 2 * c;
                float v0 = acc[mt][nt][half * 2 + 0] + bias[gn];
                float v1 = acc[mt][nt][half * 2 + 1] + bias[gn + 1];
                if (TANH) { v0 = tanhf(v0); v1 = tanhf(v1); }
                else      { v0 = f2tf32f(v0); v1 = f2tf32f(v1); }
                *(float2*)(C + (size_t)gm * N + gn) = make_float2(v0, v1);
            }
        }
    }
}

// ---------------------------------------------------------------------------
extern "C" void kernel_launch(void* const* d_in, const int* in_sizes, int n_in,
                              void* d_out, int out_size) {
    const float* x    = (const float*)d_in[0];   // node_feats [10000,256]
    const float* W1   = (const float*)d_in[1];   // [512,256]
    const float* b1   = (const float*)d_in[2];   // [256]
    const float* W2   = (const float*)d_in[3];   // [256,256]
    const float* b2   = (const float*)d_in[4];   // [256]
    const int*   esrc = (const int*)d_in[5];     // [320000]
    const int*   edst = (const int*)d_in[6];     // [320000]
    float*       out  = (float*)d_out;           // [10000,256]

    void *cat_p = nullptr, *h_p = nullptr, *w1_p = nullptr, *w2_p = nullptr;
    cudaGetSymbolAddress(&cat_p, g_cat);
    cudaGetSymbolAddress(&h_p, g_h);
    cudaGetSymbolAddress(&w1_p, g_w1r);
    cudaGetSymbolAddress(&w2_p, g_w2r);
    float* catf = (float*)cat_p;
    float* hf   = (float*)h_p;
    float* w1r  = (float*)w1_p;
    float* w2r  = (float*)w2_p;

    static bool attr_set = false;
    if (!attr_set) {
        cudaFuncSetAttribute(mma_gemm<0>,
                             cudaFuncAttributeMaxDynamicSharedMemorySize, SMEM_BYTES);
        cudaFuncSetAttribute(mma_gemm<1>,
                             cudaFuncAttributeMaxDynamicSharedMemorySize, SMEM_BYTES);
        attr_set = true;
    }

    // 1) zero cursors + round weights
    zero_cur_kernel<<<(N_NODES + 255) / 256, 256>>>();
    round_w_kernel<<<(H4 * H2 + 255) / 256, 256>>>(W1, W2);
    // 2) build padded adjacency
    fill_ell_kernel<<<(N_EDGES + 255) / 256, 256>>>(esrc, edst);
    // 3) gather + cat (tf32-rounded)
    gather_cat_kernel<<<(N_NODES * 32 + 255) / 256, 256>>>(x);
    // 4) h = cat @ W1 + b1  (rounded to tf32 on store)
    {
        dim3 grid((N_NODES + BM - 1) / BM, H2 / BN);
        mma_gemm<0><<<grid, 128, SMEM_BYTES>>>(catf, w1r, b1, hf, N_NODES, H2, H4);
    }
    // 5) out = tanh(h @ W2 + b2)
    {
        dim3 grid((N_NODES + BM - 1) / BM, H2 / BN);
        mma_gemm<1><<<grid, 128, SMEM_BYTES>>>(hf, w2r, b2, out, N_NODES, H2, H2);
    }
}

// round 10
// speedup vs baseline: 3.6493x; 1.2367x over previous
#include <cuda_runtime.h>
#include <cuda_fp16.h>
#include <math.h>
#include <stdint.h>

#define N_NODES 10000
#define N_EDGES 320000
#define H2 256          // node feature width
#define H4 512          // concat width
#define ELLW 128        // padded adjacency width

// Scratch (static __device__ arrays -- no allocation allowed)
__device__ int    g_ell[(size_t)N_NODES * ELLW];
__device__ int    g_cur[N_NODES];
__device__ __half g_xh[(size_t)N_NODES * H2];    // fp16 copy of x
__device__ __half g_cath[(size_t)N_NODES * H4];  // fp16 cat = [x, deg*x - S]
__device__ __half g_hh[(size_t)N_NODES * H2];    // fp16 GEMM1 output
__device__ __half g_w1t[(size_t)H2 * H4];        // W1^T fp16 [N=256][K=512]
__device__ __half g_w2t[(size_t)H2 * H2];        // W2^T fp16 [N=256][K=256]

// ---------------------------------------------------------------------------
// Prep: zero cursors, fp16 x copy, fp16 transposed weights. One launch.
// ---------------------------------------------------------------------------
__global__ void prep_kernel(const float* __restrict__ x,
                            const float* __restrict__ W1,
                            const float* __restrict__ W2) {
    int i = blockIdx.x * blockDim.x + threadIdx.x;
    if (i < N_NODES) g_cur[i] = 0;
    if (i < N_NODES * H2) g_xh[i] = __float2half_rn(x[i]);
    if (i < H4 * H2) {                      // W1 [512][256] -> w1t [256][512]
        int k = i >> 8, n = i & 255;
        g_w1t[(size_t)n * H4 + k] = __float2half_rn(W1[i]);
    }
    if (i < H2 * H2) {                      // W2 [256][256] -> w2t [256][256]
        int k = i >> 8, n = i & 255;
        g_w2t[(size_t)n * H2 + k] = __float2half_rn(W2[i]);
    }
}

__global__ void fill_ell_kernel(const int* __restrict__ esrc,
                                const int* __restrict__ edst) {
    int e = blockIdx.x * blockDim.x + threadIdx.x;
    if (e >= N_EDGES) return;
    int s = esrc[e];
    int d = edst[e];
    int pos = atomicAdd(&g_cur[d], 1);
    if (pos < ELLW) g_ell[((size_t)d << 7) + pos] = s;
}

// ---------------------------------------------------------------------------
// Gather + cat (fp16 in / fp16 out). One warp per node; lane owns cols
// [8*lane, 8*lane+8) = one uint4 (8 halves) per row.
// ---------------------------------------------------------------------------
union H8 { uint4 u; __half2 h[4]; };

__device__ __forceinline__ void acc8(float* a, uint4 v) {
    H8 p; p.u = v;
#pragma unroll
    for (int t = 0; t < 4; ++t) {
        float2 f = __half22float2(p.h[t]);
        a[2 * t]     += f.x;
        a[2 * t + 1] += f.y;
    }
}

__global__ __launch_bounds__(256)
void gather_cat_kernel(const float* __restrict__ x) {
    int gtid = blockIdx.x * blockDim.x + threadIdx.x;
    int node = gtid >> 5;
    int lane = gtid & 31;
    if (node >= N_NODES) return;

    int deg = g_cur[node];
    const int* __restrict__ nbr = g_ell + ((size_t)node << 7);
    const uint4* __restrict__ xh4 = (const uint4*)g_xh;   // 32 chunks/row

    float a[8];
#pragma unroll
    for (int i = 0; i < 8; ++i) a[i] = 0.f;

    int j = 0;
    for (; j + 4 <= deg; j += 4) {
        int s0 = nbr[j], s1 = nbr[j + 1], s2 = nbr[j + 2], s3 = nbr[j + 3];
        uint4 v0 = xh4[(size_t)s0 * 32 + lane];
        uint4 v1 = xh4[(size_t)s1 * 32 + lane];
        uint4 v2 = xh4[(size_t)s2 * 32 + lane];
        uint4 v3 = xh4[(size_t)s3 * 32 + lane];
        acc8(a, v0); acc8(a, v1); acc8(a, v2); acc8(a, v3);
    }
    for (; j < deg; ++j) {
        uint4 v = xh4[(size_t)nbr[j] * 32 + lane];
        acc8(a, v);
    }

    // self features (fp32, exact) for cols [8*lane, 8*lane+8)
    const float4* x4 = (const float4*)x;
    float4 xa = x4[(size_t)node * 64 + 2 * lane];
    float4 xb = x4[(size_t)node * 64 + 2 * lane + 1];
    float dg = (float)deg;

    H8 xo, po;
    xo.h[0] = __floats2half2_rn(xa.x, xa.y);
    xo.h[1] = __floats2half2_rn(xa.z, xa.w);
    xo.h[2] = __floats2half2_rn(xb.x, xb.y);
    xo.h[3] = __floats2half2_rn(xb.z, xb.w);
    po.h[0] = __floats2half2_rn(dg * xa.x - a[0], dg * xa.y - a[1]);
    po.h[1] = __floats2half2_rn(dg * xa.z - a[2], dg * xa.w - a[3]);
    po.h[2] = __floats2half2_rn(dg * xb.x - a[4], dg * xb.y - a[5]);
    po.h[3] = __floats2half2_rn(dg * xb.z - a[6], dg * xb.w - a[7]);

    uint4* cat16 = (uint4*)g_cath;          // 64 chunks/row
    cat16[(size_t)node * 64 + lane]      = xo.u;
    cat16[(size_t)node * 64 + 32 + lane] = po.u;
}

// ---------------------------------------------------------------------------
// fp16 mma.sync GEMM (m16n8k16, fp32 accumulate), cp.async pipeline.
//   C[M,N] = A[M,K] @ Bt[N,K]^T + bias
// Block tile 64x64x32, 128 threads (4 warps 2x2), warp tile 32x32.
// Both A and Bt stored [row][k] fp16 in smem, row pad LDK=40 halves (80 B)
// -> b32 fragment LDS banks (20*row + c) mod 32 all distinct: conflict-free.
// EPI: 0 = store fp16 (GEMM1 -> g_hh), 1 = tanh + fp32 store (GEMM2 -> out)
// ---------------------------------------------------------------------------
__device__ __forceinline__ void cp16(uint32_t dst, const void* src, int srcsz) {
    asm volatile("cp.async.cg.shared.global [%0], [%1], 16, %2;"
                 :: "r"(dst), "l"(src), "r"(srcsz) : "memory");
}
#define CP_COMMIT() asm volatile("cp.async.commit_group;" ::: "memory")
#define CP_WAIT(n)  asm volatile("cp.async.wait_group %0;" :: "n"(n) : "memory")

#define BM 64
#define BN 64
#define BK 32                         // k halves per stage
#define LDK 40                        // smem row length in halves (80 B)
#define A_ST (BM * LDK)               // 2560 halves = 5120 B per stage

template<int EPI>
__global__ __launch_bounds__(128, 6)
void mma_gemm(const __half* __restrict__ A, const __half* __restrict__ Bt,
              const float* __restrict__ bias, void* __restrict__ Cout,
              int M, int N, int K)
{
    __shared__ __half Asm[2 * A_ST];
    __shared__ __half Bsm[2 * A_ST];
    uint32_t a_sa = (uint32_t)__cvta_generic_to_shared(Asm);
    uint32_t b_sa = (uint32_t)__cvta_generic_to_shared(Bsm);

    const int tid  = threadIdx.x;
    const int wid  = tid >> 5;
    const int lane = tid & 31;
    const int r = lane >> 2;
    const int c = lane & 3;
    const int wm0 = (wid & 1) * 32;
    const int wn0 = (wid >> 1) * 32;
    const int m0 = blockIdx.x * BM, n0 = blockIdx.y * BN;

    float acc[2][4][4];
#pragma unroll
    for (int i = 0; i < 2; ++i)
#pragma unroll
        for (int j = 0; j < 4; ++j)
#pragma unroll
            for (int q = 0; q < 4; ++q) acc[i][j][q] = 0.f;

    const int T = K / BK;

    // cp.async: A/B each 64 rows x 4 x 16B chunks = 256 chunks, 2/thread
    auto prefetch = [&](int t, int buf) {
        uint32_t ab = a_sa + (uint32_t)buf * A_ST * 2;
        uint32_t bb = b_sa + (uint32_t)buf * A_ST * 2;
        const __half* Ap = A + (size_t)t * BK;
        const __half* Bp = Bt + (size_t)t * BK;
#pragma unroll
        for (int i = 0; i < 2; ++i) {
            int ch  = tid + 128 * i;
            int row = ch >> 2, seg = ch & 3;
            int gm  = m0 + row;
            cp16(ab + row * (LDK * 2) + seg * 16,
                 Ap + (size_t)gm * K + seg * 8, gm < M ? 16 : 0);
            cp16(bb + row * (LDK * 2) + seg * 16,
                 Bp + (size_t)(n0 + row) * K + seg * 8, 16);
        }
        CP_COMMIT();
    };

    prefetch(0, 0);

    for (int t = 0; t < T; ++t) {
        int buf = t & 1;
        if (t + 1 < T) {
            prefetch(t + 1, 1 - buf);
            CP_WAIT(1);
        } else {
            CP_WAIT(0);
        }
        __syncthreads();

        const __half* Ab = Asm + buf * A_ST;
        const __half* Bb = Bsm + buf * A_ST;

#pragma unroll
        for (int kt = 0; kt < 2; ++kt) {
            int kb = kt * 16 + 2 * c;           // half index of k-pair
            unsigned af[2][4];
#pragma unroll
            for (int mt = 0; mt < 2; ++mt) {
                int row = wm0 + mt * 16 + r;
                af[mt][0] = *(const uint32_t*)(Ab + row * LDK + kb);
                af[mt][1] = *(const uint32_t*)(Ab + (row + 8) * LDK + kb);
                af[mt][2] = *(const uint32_t*)(Ab + row * LDK + kb + 8);
                af[mt][3] = *(const uint32_t*)(Ab + (row + 8) * LDK + kb + 8);
            }
#pragma unroll
            for (int nt = 0; nt < 4; ++nt) {
                int ncol = wn0 + nt * 8 + r;
                unsigned b0 = *(const uint32_t*)(Bb + ncol * LDK + kb);
                unsigned b1 = *(const uint32_t*)(Bb + ncol * LDK + kb + 8);
#pragma unroll
                for (int mt = 0; mt < 2; ++mt) {
                    asm volatile(
                        "mma.sync.aligned.m16n8k16.row.col.f32.f16.f16.f32 "
                        "{%0,%1,%2,%3}, {%4,%5,%6,%7}, {%8,%9}, {%0,%1,%2,%3};"
                        : "+f"(acc[mt][nt][0]), "+f"(acc[mt][nt][1]),
                          "+f"(acc[mt][nt][2]), "+f"(acc[mt][nt][3])
                        : "r"(af[mt][0]), "r"(af[mt][1]),
                          "r"(af[mt][2]), "r"(af[mt][3]),
                          "r"(b0), "r"(b1));
                }
            }
        }
        __syncthreads();
    }

    // Epilogue: c0,c1 -> row r cols 2c,2c+1; c2,c3 -> row r+8.
#pragma unroll
    for (int mt = 0; mt < 2; ++mt) {
#pragma unroll
        for (int half = 0; half < 2; ++half) {
            int gm = m0 + wm0 + mt * 16 + r + half * 8;
            if (gm >= M) continue;
#pragma unroll
            for (int nt = 0; nt < 4; ++nt) {
                int gn = n0 + wn0 + nt * 8 + 2 * c;
                float v0 = acc[mt][nt][half * 2 + 0] + bias[gn];
                float v1 = acc[mt][nt][half * 2 + 1] + bias[gn + 1];
                if (EPI == 0) {
                    *(__half2*)((__half*)Cout + (size_t)gm * N + gn) =
                        __floats2half2_rn(v0, v1);
                } else {
                    *(float2*)((float*)Cout + (size_t)gm * N + gn) =
                        make_float2(tanhf(v0), tanhf(v1));
                }
            }
        }
    }
}

// ---------------------------------------------------------------------------
extern "C" void kernel_launch(void* const* d_in, const int* in_sizes, int n_in,
                              void* d_out, int out_size) {
    const float* x    = (const float*)d_in[0];   // node_feats [10000,256]
    const float* W1   = (const float*)d_in[1];   // [512,256]
    const float* b1   = (const float*)d_in[2];   // [256]
    const float* W2   = (const float*)d_in[3];   // [256,256]
    const float* b2   = (const float*)d_in[4];   // [256]
    const int*   esrc = (const int*)d_in[5];     // [320000]
    const int*   edst = (const int*)d_in[6];     // [320000]
    float*       out  = (float*)d_out;           // [10000,256]

    void *cat_p = nullptr, *h_p = nullptr, *w1_p = nullptr, *w2_p = nullptr;
    cudaGetSymbolAddress(&cat_p, g_cath);
    cudaGetSymbolAddress(&h_p, g_hh);
    cudaGetSymbolAddress(&w1_p, g_w1t);
    cudaGetSymbolAddress(&w2_p, g_w2t);
    const __half* cath = (const __half*)cat_p;
    __half*       hh   = (__half*)h_p;
    const __half* w1t  = (const __half*)w1_p;
    const __half* w2t  = (const __half*)w2_p;

    // 1) prep: zero cursors, fp16 x, fp16 transposed weights
    prep_kernel<<<(N_NODES * H2 + 255) / 256, 256>>>(x, W1, W2);
    // 2) build padded adjacency
    fill_ell_kernel<<<(N_EDGES + 255) / 256, 256>>>(esrc, edst);
    // 3) gather + cat (fp16 gather, fp16 cat)
    gather_cat_kernel<<<(N_NODES * 32 + 255) / 256, 256>>>(x);
    // 4) h = cat @ W1 + b1  (fp16 mma, fp16 store)
    {
        dim3 grid((N_NODES + BM - 1) / BM, H2 / BN);
        mma_gemm<0><<<grid, 128>>>(cath, w1t, b1, hh, N_NODES, H2, H4);
    }
    // 5) out = tanh(h @ W2 + b2)  (fp16 mma, fp32 store)
    {
        dim3 grid((N_NODES + BM - 1) / BM, H2 / BN);
        mma_gemm<1><<<grid, 128>>>(hh, w2t, b2, out, N_NODES, H2, H2);
    }
}